// round 13
// baseline (speedup 1.0000x reference)
#include <cuda_runtime.h>
#include <cuda_fp16.h>
#include <cstdint>

#define BDIM 8
#define SDIM 4096
#define EDIM 256
#define HDIM 4
#define DK   64
#define MTOT (BDIM * SDIM)   // 32768
#define NMB  (MTOT / 128)    // 256 m-blocks

// ---------------- scratch (device globals; no runtime alloc) -------------------
__device__ __half g_xh[(size_t)MTOT * EDIM];
__device__ __half g_yh[(size_t)MTOT * EDIM];
__device__ __half g_q[(size_t)MTOT * EDIM];
__device__ __half g_k[(size_t)MTOT * EDIM];
__device__ __half g_v[(size_t)MTOT * EDIM];
__device__ __half g_wh[4][EDIM * EDIM];
__device__ int    g_cnt[NMB];

// ---------------- helpers ------------------------------------------------------
__device__ __forceinline__ uint32_t smem_u32(const void* p) {
    uint32_t a;
    asm("{ .reg .u64 t; cvta.to.shared.u64 t, %1; cvt.u32.u64 %0, t; }" : "=r"(a) : "l"(p));
    return a;
}

#define CP_ASYNC16(smem, gmem) \
    asm volatile("cp.async.cg.shared.global [%0], [%1], 16;" :: "r"(smem), "l"(gmem))
#define CP_ASYNC_COMMIT() asm volatile("cp.async.commit_group;")
#define CP_ASYNC_WAIT(n)  asm volatile("cp.async.wait_group %0;" :: "n"(n))

#define LDMATRIX_X4(r0, r1, r2, r3, addr) \
    asm volatile("ldmatrix.sync.aligned.m8n8.x4.shared.b16 {%0,%1,%2,%3}, [%4];" \
        : "=r"(r0), "=r"(r1), "=r"(r2), "=r"(r3) : "r"(addr))

#define MMA16816(c, a, b0, b1) \
    asm volatile("mma.sync.aligned.m16n8k16.row.col.f32.f16.f16.f32 " \
        "{%0,%1,%2,%3}, {%4,%5,%6,%7}, {%8,%9}, {%0,%1,%2,%3};" \
        : "+f"((c)[0]), "+f"((c)[1]), "+f"((c)[2]), "+f"((c)[3]) \
        : "r"((a)[0]), "r"((a)[1]), "r"((a)[2]), "r"((a)[3]), "r"(b0), "r"(b1))

// ---------------- convert fp32 -> fp16 ------------------------------------------
__device__ __forceinline__ uint2 cvt4(float4 v) {
    __half2 p0{__float2half_rn(v.x), __float2half_rn(v.y)};
    __half2 p1{__float2half_rn(v.z), __float2half_rn(v.w)};
    uint2 H;
    H.x = *(uint32_t*)&p0; H.y = *(uint32_t*)&p1;
    return H;
}

#define X4   (MTOT * EDIM / 4)
#define W4   (EDIM * EDIM / 4)
#define ALL4 (X4 + 4 * W4)

__global__ void split_all_kernel(const float4* __restrict__ x,
                                 const float4* __restrict__ w0, const float4* __restrict__ w1,
                                 const float4* __restrict__ w2, const float4* __restrict__ w3,
                                 uint2* __restrict__ xhi, uint2* __restrict__ whi)
{
    int i = blockIdx.x * blockDim.x + threadIdx.x;
    if (i < NMB) g_cnt[i] = 0;          // reset attention counters each replay
    if (i >= ALL4) return;
    if (i < X4) {
        xhi[i] = cvt4(x[i]);
    } else {
        int j = i - X4;
        int which = j >> 14;
        int idx = j & 16383;
        const float4* src = which == 0 ? w0 : which == 1 ? w1 : which == 2 ? w2 : w3;
        whi[j] = cvt4(src[idx]);
    }
}

// ---------------- attention helpers ---------------------------------------------
__device__ __forceinline__ uint4 shfl4(uint4 v, int src) {
    uint4 r;
    r.x = __shfl_sync(0xFFFFFFFFu, v.x, src);
    r.y = __shfl_sync(0xFFFFFFFFu, v.y, src);
    r.z = __shfl_sync(0xFFFFFFFFu, v.z, src);
    r.w = __shfl_sync(0xFFFFFFFFu, v.w, src);
    return r;
}

__device__ __forceinline__ float dot8(uint4 a, uint4 b) {
    const __half2* pa = (const __half2*)&a;
    const __half2* pb = (const __half2*)&b;
    float acc = 0.0f;
#pragma unroll
    for (int w = 0; w < 4; w++) {
        float2 fa = __half22float2(pa[w]);
        float2 fb = __half22float2(pb[w]);
        acc = fmaf(fa.x, fb.x, acc);
        acc = fmaf(fa.y, fb.y, acc);
    }
    return acc;
}

// ---------------- HMMA GEMM: C = A * W^T + bias (fp16 in, fp32 accum) -----------
// CTA tile 128(M) x 64(N), BK=64, 2-stage cp.async double buffer.
// QKV variant (OT=__half): last CTA per m-block runs inline attention.
#define BM 128
#define BN 64
#define BK 64
#define NKC (EDIM / BK)             // 4
#define GT 256
#define LDA 72
#define A_TILE (BM * LDA)
#define B_TILE (BN * LDA)
#define STAGE (A_TILE + B_TILE)
#define OFF_A 0
#define OFF_W A_TILE
#define SMEM_BYTES (2 * STAGE * 2 + 512)

__device__ __forceinline__ void load_stage(uint32_t st,
                                           const __half* __restrict__ A,
                                           const __half* __restrict__ W,
                                           int m0, int n0, int k0, int tid)
{
#pragma unroll
    for (int i = 0; i < 4; i++) {
        const int c = tid + i * GT;
        const int row = c >> 3;
        const int col = (c & 7) << 3;
        CP_ASYNC16(st + OFF_A * 2 + (uint32_t)(row * LDA + col) * 2,
                   A + (size_t)(m0 + row) * EDIM + k0 + col);
    }
#pragma unroll
    for (int i = 0; i < 2; i++) {
        const int c = tid + i * GT;
        const int row = c >> 3;
        const int col = (c & 7) << 3;
        CP_ASYNC16(st + OFF_W * 2 + (uint32_t)(row * LDA + col) * 2,
                   W + (size_t)(n0 + row) * EDIM + k0 + col);
    }
}

template <typename OT>
__global__ __launch_bounds__(GT, 4)
void hmma_gemm_kernel(const __half* __restrict__ A,
                      const __half* __restrict__ Wh_all,
                      const float* __restrict__ b0p,
                      const float* __restrict__ b1p,
                      const float* __restrict__ b2p,
                      OT* __restrict__ o0,
                      OT* __restrict__ o1,
                      OT* __restrict__ o2,
                      __half* __restrict__ yout,
                      int wbase)
{
    extern __shared__ __half smem[];
    const uint32_t sb = smem_u32(smem);
    float* sbias = (float*)(smem + 2 * STAGE);

    const int tid = threadIdx.x;
    const int wid = tid >> 5;
    const int lane = tid & 31;
    const int sel = blockIdx.x >> 2;
    const int n0 = (blockIdx.x & 3) * BN;
    const int m0 = blockIdx.y * BM;
    const int warp_m = (wid & 3) * 32;
    const int warp_n = (wid >> 2) * 32;

    const __half* W = Wh_all + (size_t)(wbase + sel) * EDIM * EDIM;
    const float* bias = sel == 0 ? b0p : (sel == 1 ? b1p : b2p);
    OT* C = sel == 0 ? o0 : (sel == 1 ? o1 : o2);

    load_stage(sb, A, W, m0, n0, 0, tid);
    CP_ASYNC_COMMIT();
    load_stage(sb + STAGE * 2, A, W, m0, n0, BK, tid);
    CP_ASYNC_COMMIT();
    if (tid < BN) sbias[tid] = bias[n0 + tid];

    float acc[2][4][4];
#pragma unroll
    for (int i = 0; i < 2; i++)
#pragma unroll
        for (int j = 0; j < 4; j++)
#pragma unroll
            for (int r = 0; r < 4; r++) acc[i][j][r] = 0.0f;

    for (int kc = 0; kc < NKC; kc++) {
        if (kc < NKC - 1) CP_ASYNC_WAIT(1); else CP_ASYNC_WAIT(0);
        __syncthreads();

        const uint32_t st = sb + (kc & 1) * STAGE * 2;
        const uint32_t sA = st + OFF_A * 2;
        const uint32_t sW = st + OFF_W * 2;

#pragma unroll
        for (int ks = 0; ks < BK / 16; ks++) {
            const int k = ks * 16;
            uint32_t ah[2][4];
#pragma unroll
            for (int mf = 0; mf < 2; mf++) {
                const uint32_t off =
                    (uint32_t)((warp_m + mf * 16 + (lane & 15)) * LDA + k + ((lane >> 4) << 3)) * 2;
                LDMATRIX_X4(ah[mf][0], ah[mf][1], ah[mf][2], ah[mf][3], sA + off);
            }
#pragma unroll
            for (int nf = 0; nf < 2; nf++) {
                const uint32_t boff =
                    (uint32_t)((warp_n + nf * 16 + (lane & 7) + ((lane >> 4) << 3)) * LDA
                               + k + (((lane >> 3) & 1) << 3)) * 2;
                uint32_t bh[4];
                LDMATRIX_X4(bh[0], bh[1], bh[2], bh[3], sW + boff);
                MMA16816(acc[0][nf * 2],     ah[0], bh[0], bh[1]);
                MMA16816(acc[0][nf * 2 + 1], ah[0], bh[2], bh[3]);
                MMA16816(acc[1][nf * 2],     ah[1], bh[0], bh[1]);
                MMA16816(acc[1][nf * 2 + 1], ah[1], bh[2], bh[3]);
            }
        }
        __syncthreads();
        if (kc + 2 < NKC) {
            load_stage(st, A, W, m0, n0, (kc + 2) * BK, tid);
            CP_ASYNC_COMMIT();
        }
    }

    // epilogue: C = acc + bias
#pragma unroll
    for (int mf = 0; mf < 2; mf++) {
        const int r0 = m0 + warp_m + mf * 16 + (lane >> 2);
#pragma unroll
        for (int nf = 0; nf < 4; nf++) {
            const int colL = warp_n + nf * 8 + (lane & 3) * 2;
            const float b0 = sbias[colL], b1 = sbias[colL + 1];
            const int col = n0 + colL;
            float2 v0{acc[mf][nf][0] + b0, acc[mf][nf][1] + b1};
            float2 v1{acc[mf][nf][2] + b0, acc[mf][nf][3] + b1};
            if (sizeof(OT) == 2) {
                __half2 h0{__float2half_rn(v0.x), __float2half_rn(v0.y)};
                __half2 h1{__float2half_rn(v1.x), __float2half_rn(v1.y)};
                *(__half2*)((__half*)C + (size_t)r0 * EDIM + col) = h0;
                *(__half2*)((__half*)C + (size_t)(r0 + 8) * EDIM + col) = h1;
            } else {
                *(float2*)((float*)C + (size_t)r0 * EDIM + col) = v0;
                *(float2*)((float*)C + (size_t)(r0 + 8) * EDIM + col) = v1;
            }
        }
    }

    // ---- QKV only: last CTA of this m-block runs inline attention ----
    if (sizeof(OT) == 2) {
        __shared__ int is_last;
        __threadfence();
        __syncthreads();
        if (tid == 0) {
            int old = atomicAdd(&g_cnt[blockIdx.y], 1);
            is_last = (old == (int)gridDim.x - 1);
        }
        __syncthreads();
        if (!is_last) return;
        __threadfence();

        const __half* qg = (const __half*)o0;
        const __half* kg = (const __half*)o1;
        const __half* vg = (const __half*)o2;
        const int h = lane >> 3;          // head owned by this lane's chunk
        const int j = lane & 7;           // chunk within head

#pragma unroll 1
        for (int it = 0; it < 16; it++) {
            const int t = m0 + (wid << 4) + it;
            const uint4 q4 = ((const uint4*)(qg + (size_t)t * EDIM))[lane];
            const uint4 k4 = ((const uint4*)(kg + (size_t)t * EDIM))[lane];
            const uint4 v4 = ((const uint4*)(vg + (size_t)t * EDIM))[lane];

            float s[HDIM];
#pragma unroll
            for (int g = 0; g < HDIM; g++) {
                uint4 kgc = shfl4(k4, (g << 3) + j);
                float d = dot8(q4, kgc);
                d += __shfl_xor_sync(0xFFFFFFFFu, d, 1);
                d += __shfl_xor_sync(0xFFFFFFFFu, d, 2);
                d += __shfl_xor_sync(0xFFFFFFFFu, d, 4);
                s[g] = d * 0.125f;        // row h (this lane's head), col g
            }
            float m = fmaxf(fmaxf(s[0], s[1]), fmaxf(s[2], s[3]));
            float p[HDIM], sum = 0.0f;
#pragma unroll
            for (int g = 0; g < HDIM; g++) { p[g] = __expf(s[g] - m); sum += p[g]; }
            const float inv = 1.0f / sum;

            float2 ya[4];
#pragma unroll
            for (int w = 0; w < 4; w++) ya[w] = float2{0.0f, 0.0f};
#pragma unroll
            for (int g = 0; g < HDIM; g++) {
                uint4 vgc = shfl4(v4, (g << 3) + j);
                const float pg = p[g] * inv;
                const __half2* pv = (const __half2*)&vgc;
#pragma unroll
                for (int w = 0; w < 4; w++) {
                    float2 fv = __half22float2(pv[w]);
                    ya[w].x = fmaf(pg, fv.x, ya[w].x);
                    ya[w].y = fmaf(pg, fv.y, ya[w].y);
                }
            }
            uint4 yo;
            __half2* py = (__half2*)&yo;
#pragma unroll
            for (int w = 0; w < 4; w++)
                py[w] = __half2{__float2half_rn(ya[w].x), __float2half_rn(ya[w].y)};
            ((uint4*)(yout + (size_t)t * EDIM))[lane] = yo;
        }
        // suppress unused warning for h in release builds
        (void)h;
    }
}

// ---------------- launch --------------------------------------------------------
extern "C" void kernel_launch(void* const* d_in, const int* in_sizes, int n_in,
                              void* d_out, int out_size)
{
    const float* x  = (const float*)d_in[0];
    const float* Wq = (const float*)d_in[1];
    const float* bq = (const float*)d_in[2];
    const float* Wk = (const float*)d_in[3];
    const float* bk = (const float*)d_in[4];
    const float* Wv = (const float*)d_in[5];
    const float* bv = (const float*)d_in[6];
    const float* Wo = (const float*)d_in[7];
    const float* bo = (const float*)d_in[8];
    float* out = (float*)d_out;

    __half *xh, *yh, *q, *k, *v;
    __half (*wh)[EDIM * EDIM];
    cudaGetSymbolAddress((void**)&xh, g_xh);
    cudaGetSymbolAddress((void**)&yh, g_yh);
    cudaGetSymbolAddress((void**)&q, g_q);
    cudaGetSymbolAddress((void**)&k, g_k);
    cudaGetSymbolAddress((void**)&v, g_v);
    cudaGetSymbolAddress((void**)&wh, g_wh);

    cudaFuncSetAttribute(hmma_gemm_kernel<__half>,
                         cudaFuncAttributeMaxDynamicSharedMemorySize, SMEM_BYTES);
    cudaFuncSetAttribute(hmma_gemm_kernel<float>,
                         cudaFuncAttributeMaxDynamicSharedMemorySize, SMEM_BYTES);

    split_all_kernel<<<(ALL4 + 255) / 256, 256>>>(
        (const float4*)x, (const float4*)Wq, (const float4*)Wk,
        (const float4*)Wv, (const float4*)Wo,
        (uint2*)xh, (uint2*)wh[0]);

    // fused Q,K,V GEMM + inline attention (last CTA per m-block)
    {
        dim3 grid(12, MTOT / BM);
        hmma_gemm_kernel<__half><<<grid, GT, SMEM_BYTES>>>(
            xh, wh[0], bq, bk, bv, q, k, v, yh, 0);
    }

    // output GEMM: fp32 output to d_out
    {
        dim3 grid(4, MTOT / BM);
        hmma_gemm_kernel<float><<<grid, GT, SMEM_BYTES>>>(
            yh, wh[0], bo, bo, bo, out, out, out, nullptr, 3);
    }
}

// round 14
// speedup vs baseline: 1.2130x; 1.2130x over previous
#include <cuda_runtime.h>
#include <cuda_fp16.h>
#include <cstdint>

#define BDIM 8
#define SDIM 4096
#define EDIM 256
#define HDIM 4
#define DK   64
#define MTOT (BDIM * SDIM)   // 32768

// ---------------- scratch (device globals; no runtime alloc) -------------------
__device__ __half g_xh[(size_t)MTOT * EDIM];
__device__ __half g_yh[(size_t)MTOT * EDIM];
__device__ __half g_q[(size_t)MTOT * EDIM];
__device__ __half g_k[(size_t)MTOT * EDIM];
__device__ __half g_v[(size_t)MTOT * EDIM];
__device__ __half g_wh[4][EDIM * EDIM];

// ---------------- helpers ------------------------------------------------------
__device__ __forceinline__ uint32_t smem_u32(const void* p) {
    uint32_t a;
    asm("{ .reg .u64 t; cvta.to.shared.u64 t, %1; cvt.u32.u64 %0, t; }" : "=r"(a) : "l"(p));
    return a;
}

#define CP_ASYNC16(smem, gmem) \
    asm volatile("cp.async.cg.shared.global [%0], [%1], 16;" :: "r"(smem), "l"(gmem))
#define CP_ASYNC_COMMIT() asm volatile("cp.async.commit_group;")
#define CP_ASYNC_WAIT(n)  asm volatile("cp.async.wait_group %0;" :: "n"(n))

#define LDMATRIX_X4(r0, r1, r2, r3, addr) \
    asm volatile("ldmatrix.sync.aligned.m8n8.x4.shared.b16 {%0,%1,%2,%3}, [%4];" \
        : "=r"(r0), "=r"(r1), "=r"(r2), "=r"(r3) : "r"(addr))

#define MMA16816(c, a, b0, b1) \
    asm volatile("mma.sync.aligned.m16n8k16.row.col.f32.f16.f16.f32 " \
        "{%0,%1,%2,%3}, {%4,%5,%6,%7}, {%8,%9}, {%0,%1,%2,%3};" \
        : "+f"((c)[0]), "+f"((c)[1]), "+f"((c)[2]), "+f"((c)[3]) \
        : "r"((a)[0]), "r"((a)[1]), "r"((a)[2]), "r"((a)[3]), "r"(b0), "r"(b1))

// ---------------- convert fp32 -> fp16 ------------------------------------------
__device__ __forceinline__ uint2 cvt4(float4 v) {
    __half2 p0{__float2half_rn(v.x), __float2half_rn(v.y)};
    __half2 p1{__float2half_rn(v.z), __float2half_rn(v.w)};
    uint2 H;
    H.x = *(uint32_t*)&p0; H.y = *(uint32_t*)&p1;
    return H;
}

#define X8   (MTOT * EDIM / 8)          // 1048576 8-float groups in x
#define W8   (EDIM * EDIM / 8)          // 8192 per weight
#define ALL8 (X8 + 4 * W8)              // 1081344

// each thread: two float4 loads -> one uint4 (8 fp16) store
__global__ void split_all_kernel(const float4* __restrict__ x,
                                 const float4* __restrict__ w0, const float4* __restrict__ w1,
                                 const float4* __restrict__ w2, const float4* __restrict__ w3,
                                 uint4* __restrict__ xhi, uint4* __restrict__ whi)
{
    int i = blockIdx.x * blockDim.x + threadIdx.x;
    if (i >= ALL8) return;
    const float4* src;
    uint4* dst;
    int j;
    if (i < X8) {
        src = x; dst = xhi; j = i;
    } else {
        int t = i - X8;
        int which = t >> 13;            // W8 = 8192 = 2^13
        j = t & 8191;
        src = which == 0 ? w0 : which == 1 ? w1 : which == 2 ? w2 : w3;
        dst = whi + (size_t)which * W8;
    }
    uint2 lo = cvt4(src[2 * j]);
    uint2 hi = cvt4(src[2 * j + 1]);
    dst[j] = uint4{lo.x, lo.y, hi.x, hi.y};
}

// ---------------- HMMA GEMM: C = A * W^T + bias (fp16 in, fp32 accum) -----------
// CTA tile 128(M) x 64(N), BK=64, 2-stage cp.async double buffer.
#define BM 128
#define BN 64
#define BK 64
#define NKC (EDIM / BK)             // 4
#define GT 256
#define LDA 72
#define A_TILE (BM * LDA)
#define B_TILE (BN * LDA)
#define STAGE (A_TILE + B_TILE)
#define OFF_A 0
#define OFF_W A_TILE
#define SMEM_BYTES (2 * STAGE * 2 + 512)

__device__ __forceinline__ void load_stage(uint32_t st,
                                           const __half* __restrict__ A,
                                           const __half* __restrict__ W,
                                           int m0, int n0, int k0, int tid)
{
#pragma unroll
    for (int i = 0; i < 4; i++) {
        const int c = tid + i * GT;
        const int row = c >> 3;
        const int col = (c & 7) << 3;
        CP_ASYNC16(st + OFF_A * 2 + (uint32_t)(row * LDA + col) * 2,
                   A + (size_t)(m0 + row) * EDIM + k0 + col);
    }
#pragma unroll
    for (int i = 0; i < 2; i++) {
        const int c = tid + i * GT;
        const int row = c >> 3;
        const int col = (c & 7) << 3;
        CP_ASYNC16(st + OFF_W * 2 + (uint32_t)(row * LDA + col) * 2,
                   W + (size_t)(n0 + row) * EDIM + k0 + col);
    }
}

template <typename OT>
__global__ __launch_bounds__(GT, 4)
void hmma_gemm_kernel(const __half* __restrict__ A,
                      const __half* __restrict__ Wh_all,
                      const float* __restrict__ b0p,
                      const float* __restrict__ b1p,
                      const float* __restrict__ b2p,
                      OT* __restrict__ o0,
                      OT* __restrict__ o1,
                      OT* __restrict__ o2,
                      int wbase)
{
    extern __shared__ __half smem[];
    const uint32_t sb = smem_u32(smem);
    float* sbias = (float*)(smem + 2 * STAGE);

    const int tid = threadIdx.x;
    const int wid = tid >> 5;
    const int lane = tid & 31;
    const int sel = blockIdx.x >> 2;
    const int n0 = (blockIdx.x & 3) * BN;
    const int m0 = blockIdx.y * BM;
    const int warp_m = (wid & 3) * 32;
    const int warp_n = (wid >> 2) * 32;

    const __half* W = Wh_all + (size_t)(wbase + sel) * EDIM * EDIM;
    const float* bias = sel == 0 ? b0p : (sel == 1 ? b1p : b2p);
    OT* C = sel == 0 ? o0 : (sel == 1 ? o1 : o2);

    load_stage(sb, A, W, m0, n0, 0, tid);
    CP_ASYNC_COMMIT();
    load_stage(sb + STAGE * 2, A, W, m0, n0, BK, tid);
    CP_ASYNC_COMMIT();
    if (tid < BN) sbias[tid] = bias[n0 + tid];

    float acc[2][4][4];
#pragma unroll
    for (int i = 0; i < 2; i++)
#pragma unroll
        for (int j = 0; j < 4; j++)
#pragma unroll
            for (int r = 0; r < 4; r++) acc[i][j][r] = 0.0f;

    for (int kc = 0; kc < NKC; kc++) {
        if (kc < NKC - 1) CP_ASYNC_WAIT(1); else CP_ASYNC_WAIT(0);
        __syncthreads();

        const uint32_t st = sb + (kc & 1) * STAGE * 2;
        const uint32_t sA = st + OFF_A * 2;
        const uint32_t sW = st + OFF_W * 2;

#pragma unroll
        for (int ks = 0; ks < BK / 16; ks++) {
            const int k = ks * 16;
            uint32_t ah[2][4];
#pragma unroll
            for (int mf = 0; mf < 2; mf++) {
                const uint32_t off =
                    (uint32_t)((warp_m + mf * 16 + (lane & 15)) * LDA + k + ((lane >> 4) << 3)) * 2;
                LDMATRIX_X4(ah[mf][0], ah[mf][1], ah[mf][2], ah[mf][3], sA + off);
            }
#pragma unroll
            for (int nf = 0; nf < 2; nf++) {
                const uint32_t boff =
                    (uint32_t)((warp_n + nf * 16 + (lane & 7) + ((lane >> 4) << 3)) * LDA
                               + k + (((lane >> 3) & 1) << 3)) * 2;
                uint32_t bh[4];
                LDMATRIX_X4(bh[0], bh[1], bh[2], bh[3], sW + boff);
                MMA16816(acc[0][nf * 2],     ah[0], bh[0], bh[1]);
                MMA16816(acc[0][nf * 2 + 1], ah[0], bh[2], bh[3]);
                MMA16816(acc[1][nf * 2],     ah[1], bh[0], bh[1]);
                MMA16816(acc[1][nf * 2 + 1], ah[1], bh[2], bh[3]);
            }
        }
        __syncthreads();
        if (kc + 2 < NKC) {
            load_stage(st, A, W, m0, n0, (kc + 2) * BK, tid);
            CP_ASYNC_COMMIT();
        }
    }

    // epilogue: C = acc + bias
#pragma unroll
    for (int mf = 0; mf < 2; mf++) {
        const int r0 = m0 + warp_m + mf * 16 + (lane >> 2);
#pragma unroll
        for (int nf = 0; nf < 4; nf++) {
            const int colL = warp_n + nf * 8 + (lane & 3) * 2;
            const float b0 = sbias[colL], b1 = sbias[colL + 1];
            const int col = n0 + colL;
            float2 v0{acc[mf][nf][0] + b0, acc[mf][nf][1] + b1};
            float2 v1{acc[mf][nf][2] + b0, acc[mf][nf][3] + b1};
            if (sizeof(OT) == 2) {
                __half2 h0{__float2half_rn(v0.x), __float2half_rn(v0.y)};
                __half2 h1{__float2half_rn(v1.x), __float2half_rn(v1.y)};
                *(__half2*)((__half*)C + (size_t)r0 * EDIM + col) = h0;
                *(__half2*)((__half*)C + (size_t)(r0 + 8) * EDIM + col) = h1;
            } else {
                *(float2*)((float*)C + (size_t)r0 * EDIM + col) = v0;
                *(float2*)((float*)C + (size_t)(r0 + 8) * EDIM + col) = v1;
            }
        }
    }
}

// ---------------- attention over heads (warp-cooperative, uint4 loads) ----------
__device__ __forceinline__ uint4 shfl4(uint4 v, int src) {
    uint4 r;
    r.x = __shfl_sync(0xFFFFFFFFu, v.x, src);
    r.y = __shfl_sync(0xFFFFFFFFu, v.y, src);
    r.z = __shfl_sync(0xFFFFFFFFu, v.z, src);
    r.w = __shfl_sync(0xFFFFFFFFu, v.w, src);
    return r;
}

__device__ __forceinline__ float dot8(uint4 a, uint4 b) {
    const __half2* pa = (const __half2*)&a;
    const __half2* pb = (const __half2*)&b;
    float acc = 0.0f;
#pragma unroll
    for (int w = 0; w < 4; w++) {
        float2 fa = __half22float2(pa[w]);
        float2 fb = __half22float2(pb[w]);
        acc = fmaf(fa.x, fb.x, acc);
        acc = fmaf(fa.y, fb.y, acc);
    }
    return acc;
}

// lane = (h, j): h = lane>>3 head, j = lane&7 chunk of 8 halves within head
__global__ __launch_bounds__(256)
void attn_heads_kernel(const __half* __restrict__ q,
                       const __half* __restrict__ k,
                       const __half* __restrict__ v,
                       __half* __restrict__ yh)
{
    const int t = blockIdx.x * 8 + (threadIdx.x >> 5);
    const int lane = threadIdx.x & 31;
    const int j = lane & 7;

    const uint4 q4 = ((const uint4*)(q + (size_t)t * EDIM))[lane];
    const uint4 k4 = ((const uint4*)(k + (size_t)t * EDIM))[lane];
    const uint4 v4 = ((const uint4*)(v + (size_t)t * EDIM))[lane];

    float s[HDIM];
#pragma unroll
    for (int g = 0; g < HDIM; g++) {
        uint4 kgc = shfl4(k4, (g << 3) + j);
        float d = dot8(q4, kgc);
        d += __shfl_xor_sync(0xFFFFFFFFu, d, 1);
        d += __shfl_xor_sync(0xFFFFFFFFu, d, 2);
        d += __shfl_xor_sync(0xFFFFFFFFu, d, 4);
        s[g] = d * 0.125f;                  // score(row h of this lane, col g)
    }
    float m = fmaxf(fmaxf(s[0], s[1]), fmaxf(s[2], s[3]));
    float p[HDIM], sum = 0.0f;
#pragma unroll
    for (int g = 0; g < HDIM; g++) { p[g] = __expf(s[g] - m); sum += p[g]; }
    const float inv = 1.0f / sum;

    float2 ya[4];
#pragma unroll
    for (int w = 0; w < 4; w++) ya[w] = float2{0.0f, 0.0f};
#pragma unroll
    for (int g = 0; g < HDIM; g++) {
        uint4 vgc = shfl4(v4, (g << 3) + j);
        const float pg = p[g] * inv;
        const __half2* pv = (const __half2*)&vgc;
#pragma unroll
        for (int w = 0; w < 4; w++) {
            float2 fv = __half22float2(pv[w]);
            ya[w].x = fmaf(pg, fv.x, ya[w].x);
            ya[w].y = fmaf(pg, fv.y, ya[w].y);
        }
    }
    uint4 yo;
    __half2* py = (__half2*)&yo;
#pragma unroll
    for (int w = 0; w < 4; w++)
        py[w] = __half2{__float2half_rn(ya[w].x), __float2half_rn(ya[w].y)};
    ((uint4*)(yh + (size_t)t * EDIM))[lane] = yo;
}

// ---------------- launch --------------------------------------------------------
extern "C" void kernel_launch(void* const* d_in, const int* in_sizes, int n_in,
                              void* d_out, int out_size)
{
    const float* x  = (const float*)d_in[0];
    const float* Wq = (const float*)d_in[1];
    const float* bq = (const float*)d_in[2];
    const float* Wk = (const float*)d_in[3];
    const float* bk = (const float*)d_in[4];
    const float* Wv = (const float*)d_in[5];
    const float* bv = (const float*)d_in[6];
    const float* Wo = (const float*)d_in[7];
    const float* bo = (const float*)d_in[8];
    float* out = (float*)d_out;

    __half *xh, *yh, *q, *k, *v;
    __half (*wh)[EDIM * EDIM];
    cudaGetSymbolAddress((void**)&xh, g_xh);
    cudaGetSymbolAddress((void**)&yh, g_yh);
    cudaGetSymbolAddress((void**)&q, g_q);
    cudaGetSymbolAddress((void**)&k, g_k);
    cudaGetSymbolAddress((void**)&v, g_v);
    cudaGetSymbolAddress((void**)&wh, g_wh);

    cudaFuncSetAttribute(hmma_gemm_kernel<__half>,
                         cudaFuncAttributeMaxDynamicSharedMemorySize, SMEM_BYTES);
    cudaFuncSetAttribute(hmma_gemm_kernel<float>,
                         cudaFuncAttributeMaxDynamicSharedMemorySize, SMEM_BYTES);

    split_all_kernel<<<(ALL8 + 255) / 256, 256>>>(
        (const float4*)x, (const float4*)Wq, (const float4*)Wk,
        (const float4*)Wv, (const float4*)Wo,
        (uint4*)xh, (uint4*)wh[0]);

    // fused Q,K,V GEMM: grid.x = 3 weights x 4 n-tiles; fp16 outputs
    {
        dim3 grid(12, MTOT / BM);
        hmma_gemm_kernel<__half><<<grid, GT, SMEM_BYTES>>>(
            xh, wh[0], bq, bk, bv, q, k, v, 0);
    }

    attn_heads_kernel<<<MTOT / 8, 256>>>(q, k, v, yh);

    // output GEMM: fp32 output to d_out
    {
        dim3 grid(4, MTOT / BM);
        hmma_gemm_kernel<float><<<grid, GT, SMEM_BYTES>>>(
            yh, wh[0], bo, bo, bo, out, out, out, 3);
    }
}

// round 16
// speedup vs baseline: 1.2909x; 1.0643x over previous
#include <cuda_runtime.h>
#include <cuda_fp16.h>
#include <cstdint>

#define BDIM 8
#define SDIM 4096
#define EDIM 256
#define HDIM 4
#define DK   64
#define MTOT (BDIM * SDIM)   // 32768

// ---------------- scratch (device globals; no runtime alloc) -------------------
__device__ __half g_xh[(size_t)MTOT * EDIM];
__device__ __half g_yh[(size_t)MTOT * EDIM];
__device__ __half g_q[(size_t)MTOT * EDIM];
__device__ __half g_k[(size_t)MTOT * EDIM];
__device__ __half g_v[(size_t)MTOT * EDIM];
__device__ __half g_wh[4][EDIM * EDIM];

// ---------------- helpers ------------------------------------------------------
__device__ __forceinline__ uint32_t smem_u32(const void* p) {
    uint32_t a;
    asm("{ .reg .u64 t; cvta.to.shared.u64 t, %1; cvt.u32.u64 %0, t; }" : "=r"(a) : "l"(p));
    return a;
}

#define CP_ASYNC16(smem, gmem) \
    asm volatile("cp.async.cg.shared.global [%0], [%1], 16;" :: "r"(smem), "l"(gmem))
#define CP_ASYNC_COMMIT() asm volatile("cp.async.commit_group;")
#define CP_ASYNC_WAIT(n)  asm volatile("cp.async.wait_group %0;" :: "n"(n))

#define LDMATRIX_X4(r0, r1, r2, r3, addr) \
    asm volatile("ldmatrix.sync.aligned.m8n8.x4.shared.b16 {%0,%1,%2,%3}, [%4];" \
        : "=r"(r0), "=r"(r1), "=r"(r2), "=r"(r3) : "r"(addr))

#define MMA16816(c, a, b0, b1) \
    asm volatile("mma.sync.aligned.m16n8k16.row.col.f32.f16.f16.f32 " \
        "{%0,%1,%2,%3}, {%4,%5,%6,%7}, {%8,%9}, {%0,%1,%2,%3};" \
        : "+f"((c)[0]), "+f"((c)[1]), "+f"((c)[2]), "+f"((c)[3]) \
        : "r"((a)[0]), "r"((a)[1]), "r"((a)[2]), "r"((a)[3]), "r"(b0), "r"(b1))

// ---------------- convert fp32 -> fp16 ------------------------------------------
__device__ __forceinline__ uint2 cvt4(float4 v) {
    __half2 p0{__float2half_rn(v.x), __float2half_rn(v.y)};
    __half2 p1{__float2half_rn(v.z), __float2half_rn(v.w)};
    uint2 H;
    H.x = *(uint32_t*)&p0; H.y = *(uint32_t*)&p1;
    return H;
}

#define X8   (MTOT * EDIM / 8)
#define W8   (EDIM * EDIM / 8)
#define ALL8 (X8 + 4 * W8)

__global__ void split_all_kernel(const float4* __restrict__ x,
                                 const float4* __restrict__ w0, const float4* __restrict__ w1,
                                 const float4* __restrict__ w2, const float4* __restrict__ w3,
                                 uint4* __restrict__ xhi, uint4* __restrict__ whi)
{
    int i = blockIdx.x * blockDim.x + threadIdx.x;
    if (i >= ALL8) return;
    const float4* src;
    uint4* dst;
    int j;
    if (i < X8) {
        src = x; dst = xhi; j = i;
    } else {
        int t = i - X8;
        int which = t >> 13;
        j = t & 8191;
        src = which == 0 ? w0 : which == 1 ? w1 : which == 2 ? w2 : w3;
        dst = whi + (size_t)which * W8;
    }
    uint2 lo = cvt4(src[2 * j]);
    uint2 hi = cvt4(src[2 * j + 1]);
    dst[j] = uint4{lo.x, lo.y, hi.x, hi.y};
}

// ---------------- HMMA GEMM: C = A * W^T + bias (fp16 in, fp32 accum) -----------
// CTA tile 128(M) x 64(N), BK=64, 2-stage cp.async double buffer,
// register double-buffered LDSM fragments (MMA at ks uses frags loaded at ks-1).
#define BM 128
#define BN 64
#define BK 64
#define NKC (EDIM / BK)             // 4
#define GT 256
#define LDA 72
#define A_TILE (BM * LDA)
#define B_TILE (BN * LDA)
#define STAGE (A_TILE + B_TILE)
#define OFF_A 0
#define OFF_W A_TILE
#define SMEM_BYTES (2 * STAGE * 2 + 512)

__device__ __forceinline__ void load_stage(uint32_t st,
                                           const __half* __restrict__ A,
                                           const __half* __restrict__ W,
                                           int m0, int n0, int k0, int tid)
{
#pragma unroll
    for (int i = 0; i < 4; i++) {
        const int c = tid + i * GT;
        const int row = c >> 3;
        const int col = (c & 7) << 3;
        CP_ASYNC16(st + OFF_A * 2 + (uint32_t)(row * LDA + col) * 2,
                   A + (size_t)(m0 + row) * EDIM + k0 + col);
    }
#pragma unroll
    for (int i = 0; i < 2; i++) {
        const int c = tid + i * GT;
        const int row = c >> 3;
        const int col = (c & 7) << 3;
        CP_ASYNC16(st + OFF_W * 2 + (uint32_t)(row * LDA + col) * 2,
                   W + (size_t)(n0 + row) * EDIM + k0 + col);
    }
}

template <typename OT>
__global__ __launch_bounds__(GT, 3)
void hmma_gemm_kernel(const __half* __restrict__ A,
                      const __half* __restrict__ Wh_all,
                      const float* __restrict__ b0p,
                      const float* __restrict__ b1p,
                      const float* __restrict__ b2p,
                      OT* __restrict__ o0,
                      OT* __restrict__ o1,
                      OT* __restrict__ o2,
                      int wbase)
{
    extern __shared__ __half smem[];
    const uint32_t sb = smem_u32(smem);
    float* sbias = (float*)(smem + 2 * STAGE);

    const int tid = threadIdx.x;
    const int wid = tid >> 5;
    const int lane = tid & 31;
    const int sel = blockIdx.x >> 2;
    const int n0 = (blockIdx.x & 3) * BN;
    const int m0 = blockIdx.y * BM;
    const int warp_m = (wid & 3) * 32;
    const int warp_n = (wid >> 2) * 32;

    const __half* W = Wh_all + (size_t)(wbase + sel) * EDIM * EDIM;
    const float* bias = sel == 0 ? b0p : (sel == 1 ? b1p : b2p);
    OT* C = sel == 0 ? o0 : (sel == 1 ? o1 : o2);

    load_stage(sb, A, W, m0, n0, 0, tid);
    CP_ASYNC_COMMIT();
    load_stage(sb + STAGE * 2, A, W, m0, n0, BK, tid);
    CP_ASYNC_COMMIT();
    if (tid < BN) sbias[tid] = bias[n0 + tid];

    float acc[2][4][4];
#pragma unroll
    for (int i = 0; i < 2; i++)
#pragma unroll
        for (int j = 0; j < 4; j++)
#pragma unroll
            for (int r = 0; r < 4; r++) acc[i][j][r] = 0.0f;

    // precomputed per-thread LDSM base offsets (within a stage)
    const uint32_t aoff0 = (uint32_t)((warp_m + (lane & 15)) * LDA + ((lane >> 4) << 3)) * 2;
    const uint32_t aoff1 = (uint32_t)((warp_m + 16 + (lane & 15)) * LDA + ((lane >> 4) << 3)) * 2;
    const uint32_t boff0 = (uint32_t)((warp_n + (lane & 7) + ((lane >> 4) << 3)) * LDA
                                      + (((lane >> 3) & 1) << 3)) * 2;
    const uint32_t boff1 = (uint32_t)((warp_n + 16 + (lane & 7) + ((lane >> 4) << 3)) * LDA
                                      + (((lane >> 3) & 1) << 3)) * 2;

    uint32_t af[2][2][4];   // [buf][mf][frag]
    uint32_t bf[2][2][4];   // [buf][nf][frag]

    for (int kc = 0; kc < NKC; kc++) {
        if (kc < NKC - 1) CP_ASYNC_WAIT(1); else CP_ASYNC_WAIT(0);
        __syncthreads();

        const uint32_t st = sb + (kc & 1) * STAGE * 2;
        const uint32_t sA = st + OFF_A * 2;
        const uint32_t sW = st + OFF_W * 2;

        // preload fragments for ks=0 into buf 0
        LDMATRIX_X4(af[0][0][0], af[0][0][1], af[0][0][2], af[0][0][3], sA + aoff0);
        LDMATRIX_X4(af[0][1][0], af[0][1][1], af[0][1][2], af[0][1][3], sA + aoff1);
        LDMATRIX_X4(bf[0][0][0], bf[0][0][1], bf[0][0][2], bf[0][0][3], sW + boff0);
        LDMATRIX_X4(bf[0][1][0], bf[0][1][1], bf[0][1][2], bf[0][1][3], sW + boff1);

#pragma unroll
        for (int ks = 0; ks < BK / 16; ks++) {
            const int cur = ks & 1;
            const int nxt = cur ^ 1;
            if (ks < BK / 16 - 1) {
                const uint32_t kb = (uint32_t)(ks + 1) * 32;   // 16 halves * 2B
                LDMATRIX_X4(af[nxt][0][0], af[nxt][0][1], af[nxt][0][2], af[nxt][0][3],
                            sA + aoff0 + kb);
                LDMATRIX_X4(af[nxt][1][0], af[nxt][1][1], af[nxt][1][2], af[nxt][1][3],
                            sA + aoff1 + kb);
                LDMATRIX_X4(bf[nxt][0][0], bf[nxt][0][1], bf[nxt][0][2], bf[nxt][0][3],
                            sW + boff0 + kb);
                LDMATRIX_X4(bf[nxt][1][0], bf[nxt][1][1], bf[nxt][1][2], bf[nxt][1][3],
                            sW + boff1 + kb);
            }
#pragma unroll
            for (int nf = 0; nf < 2; nf++) {
                MMA16816(acc[0][nf * 2],     af[cur][0], bf[cur][nf][0], bf[cur][nf][1]);
                MMA16816(acc[0][nf * 2 + 1], af[cur][0], bf[cur][nf][2], bf[cur][nf][3]);
                MMA16816(acc[1][nf * 2],     af[cur][1], bf[cur][nf][0], bf[cur][nf][1]);
                MMA16816(acc[1][nf * 2 + 1], af[cur][1], bf[cur][nf][2], bf[cur][nf][3]);
            }
        }
        __syncthreads();
        if (kc + 2 < NKC) {
            load_stage(st, A, W, m0, n0, (kc + 2) * BK, tid);
            CP_ASYNC_COMMIT();
        }
    }

    // epilogue: C = acc + bias
#pragma unroll
    for (int mf = 0; mf < 2; mf++) {
        const int r0 = m0 + warp_m + mf * 16 + (lane >> 2);
#pragma unroll
        for (int nf = 0; nf < 4; nf++) {
            const int colL = warp_n + nf * 8 + (lane & 3) * 2;
            const float b0 = sbias[colL], b1 = sbias[colL + 1];
            const int col = n0 + colL;
            float2 v0{acc[mf][nf][0] + b0, acc[mf][nf][1] + b1};
            float2 v1{acc[mf][nf][2] + b0, acc[mf][nf][3] + b1};
            if (sizeof(OT) == 2) {
                __half2 h0{__float2half_rn(v0.x), __float2half_rn(v0.y)};
                __half2 h1{__float2half_rn(v1.x), __float2half_rn(v1.y)};
                *(__half2*)((__half*)C + (size_t)r0 * EDIM + col) = h0;
                *(__half2*)((__half*)C + (size_t)(r0 + 8) * EDIM + col) = h1;
            } else {
                *(float2*)((float*)C + (size_t)r0 * EDIM + col) = v0;
                *(float2*)((float*)C + (size_t)(r0 + 8) * EDIM + col) = v1;
            }
        }
    }
}

// ---------------- attention over heads (warp-cooperative, uint4 loads) ----------
__device__ __forceinline__ uint4 shfl4(uint4 v, int src) {
    uint4 r;
    r.x = __shfl_sync(0xFFFFFFFFu, v.x, src);
    r.y = __shfl_sync(0xFFFFFFFFu, v.y, src);
    r.z = __shfl_sync(0xFFFFFFFFu, v.z, src);
    r.w = __shfl_sync(0xFFFFFFFFu, v.w, src);
    return r;
}

__device__ __forceinline__ float dot8(uint4 a, uint4 b) {
    const __half2* pa = (const __half2*)&a;
    const __half2* pb = (const __half2*)&b;
    float acc = 0.0f;
#pragma unroll
    for (int w = 0; w < 4; w++) {
        float2 fa = __half22float2(pa[w]);
        float2 fb = __half22float2(pb[w]);
        acc = fmaf(fa.x, fb.x, acc);
        acc = fmaf(fa.y, fb.y, acc);
    }
    return acc;
}

__global__ __launch_bounds__(256)
void attn_heads_kernel(const __half* __restrict__ q,
                       const __half* __restrict__ k,
                       const __half* __restrict__ v,
                       __half* __restrict__ yh)
{
    const int t = blockIdx.x * 8 + (threadIdx.x >> 5);
    const int lane = threadIdx.x & 31;
    const int j = lane & 7;

    const uint4 q4 = ((const uint4*)(q + (size_t)t * EDIM))[lane];
    const uint4 k4 = ((const uint4*)(k + (size_t)t * EDIM))[lane];
    const uint4 v4 = ((const uint4*)(v + (size_t)t * EDIM))[lane];

    float s[HDIM];
#pragma unroll
    for (int g = 0; g < HDIM; g++) {
        uint4 kgc = shfl4(k4, (g << 3) + j);
        float d = dot8(q4, kgc);
        d += __shfl_xor_sync(0xFFFFFFFFu, d, 1);
        d += __shfl_xor_sync(0xFFFFFFFFu, d, 2);
        d += __shfl_xor_sync(0xFFFFFFFFu, d, 4);
        s[g] = d * 0.125f;
    }
    float m = fmaxf(fmaxf(s[0], s[1]), fmaxf(s[2], s[3]));
    float p[HDIM], sum = 0.0f;
#pragma unroll
    for (int g = 0; g < HDIM; g++) { p[g] = __expf(s[g] - m); sum += p[g]; }
    const float inv = 1.0f / sum;

    float2 ya[4];
#pragma unroll
    for (int w = 0; w < 4; w++) ya[w] = float2{0.0f, 0.0f};
#pragma unroll
    for (int g = 0; g < HDIM; g++) {
        uint4 vgc = shfl4(v4, (g << 3) + j);
        const float pg = p[g] * inv;
        const __half2* pv = (const __half2*)&vgc;
#pragma unroll
        for (int w = 0; w < 4; w++) {
            float2 fv = __half22float2(pv[w]);
            ya[w].x = fmaf(pg, fv.x, ya[w].x);
            ya[w].y = fmaf(pg, fv.y, ya[w].y);
        }
    }
    uint4 yo;
    __half2* py = (__half2*)&yo;
#pragma unroll
    for (int w = 0; w < 4; w++)
        py[w] = __half2{__float2half_rn(ya[w].x), __float2half_rn(ya[w].y)};
    ((uint4*)(yh + (size_t)t * EDIM))[lane] = yo;
}

// ---------------- launch --------------------------------------------------------
extern "C" void kernel_launch(void* const* d_in, const int* in_sizes, int n_in,
                              void* d_out, int out_size)
{
    const float* x  = (const float*)d_in[0];
    const float* Wq = (const float*)d_in[1];
    const float* bq = (const float*)d_in[2];
    const float* Wk = (const float*)d_in[3];
    const float* bk = (const float*)d_in[4];
    const float* Wv = (const float*)d_in[5];
    const float* bv = (const float*)d_in[6];
    const float* Wo = (const float*)d_in[7];
    const float* bo = (const float*)d_in[8];
    float* out = (float*)d_out;

    __half *xh, *yh, *q, *k, *v;
    __half (*wh)[EDIM * EDIM];
    cudaGetSymbolAddress((void**)&xh, g_xh);
    cudaGetSymbolAddress((void**)&yh, g_yh);
    cudaGetSymbolAddress((void**)&q, g_q);
    cudaGetSymbolAddress((void**)&k, g_k);
    cudaGetSymbolAddress((void**)&v, g_v);
    cudaGetSymbolAddress((void**)&wh, g_wh);

    cudaFuncSetAttribute(hmma_gemm_kernel<__half>,
                         cudaFuncAttributeMaxDynamicSharedMemorySize, SMEM_BYTES);
    cudaFuncSetAttribute(hmma_gemm_kernel<float>,
                         cudaFuncAttributeMaxDynamicSharedMemorySize, SMEM_BYTES);

    split_all_kernel<<<(ALL8 + 255) / 256, 256>>>(
        (const float4*)x, (const float4*)Wq, (const float4*)Wk,
        (const float4*)Wv, (const float4*)Wo,
        (uint4*)xh, (uint4*)wh[0]);

    // fused Q,K,V GEMM: grid.x = 3 weights x 4 n-tiles; fp16 outputs
    {
        dim3 grid(12, MTOT / BM);
        hmma_gemm_kernel<__half><<<grid, GT, SMEM_BYTES>>>(
            xh, wh[0], bq, bk, bv, q, k, v, 0);
    }

    attn_heads_kernel<<<MTOT / 8, 256>>>(q, k, v, yh);

    // output GEMM: fp32 output to d_out
    {
        dim3 grid(4, MTOT / BM);
        hmma_gemm_kernel<float><<<grid, GT, SMEM_BYTES>>>(
            yh, wh[0], bo, bo, bo, out, out, out, 3);
    }
}